// round 1
// baseline (speedup 1.0000x reference)
#include <cuda_runtime.h>
#include <cuda_bf16.h>

#define HIDDEN 2048
#define INTER  1408
#define TOP_K  4

// Scratch for weighted intermediate activations: topk_w[e] * silu(gate)*up
__device__ float g_inter[TOP_K * INTER];

// ---------------------------------------------------------------------------
// Kernel 1: for each selected expert e and each intermediate row i:
//   g = dot(gate[ex][i][:], x);  u = dot(up[ex][i][:], x);
//   g_inter[e][i] = topk_w[e] * silu(g) * u
// grid: (INTER/8 = 176, TOP_K), block: 256 threads (8 warps, 1 row per warp)
// ---------------------------------------------------------------------------
__global__ __launch_bounds__(256)
void moe_gate_up_kernel(const float* __restrict__ x,
                        const int*   __restrict__ topk_idx,
                        const float* __restrict__ topk_w,
                        const float* __restrict__ gate_all,
                        const float* __restrict__ up_all)
{
    __shared__ float4 x_s[HIDDEN / 4];   // 8 KB

    const int tid  = threadIdx.x;
    const int lane = tid & 31;
    const int warp = tid >> 5;

    // Stage x into shared memory: 512 float4 / 256 threads = 2 each
    const float4* x4 = reinterpret_cast<const float4*>(x);
    x_s[tid]       = x4[tid];
    x_s[tid + 256] = x4[tid + 256];
    __syncthreads();

    const int e   = blockIdx.y;                 // expert slot 0..3
    const int row = blockIdx.x * 8 + warp;      // 0..1407
    const long long ex = topk_idx[e];

    const float4* g4 = reinterpret_cast<const float4*>(
        gate_all + (ex * INTER + row) * (long long)HIDDEN);
    const float4* u4 = reinterpret_cast<const float4*>(
        up_all   + (ex * INTER + row) * (long long)HIDDEN);

    float gacc = 0.f, uacc = 0.f;
    // 512 float4 per row, 32 lanes -> 16 iterations
#pragma unroll
    for (int j = 0; j < 16; j++) {
        const int idx = j * 32 + lane;
        const float4 xv = x_s[idx];
        const float4 gv = g4[idx];
        const float4 uv = u4[idx];
        gacc += gv.x * xv.x + gv.y * xv.y + gv.z * xv.z + gv.w * xv.w;
        uacc += uv.x * xv.x + uv.y * xv.y + uv.z * xv.z + uv.w * xv.w;
    }

    // warp reduce
#pragma unroll
    for (int off = 16; off > 0; off >>= 1) {
        gacc += __shfl_xor_sync(0xFFFFFFFFu, gacc, off);
        uacc += __shfl_xor_sync(0xFFFFFFFFu, uacc, off);
    }

    if (lane == 0) {
        const float w = topk_w[e];
        const float silu = gacc / (1.0f + __expf(-gacc));
        g_inter[e * INTER + row] = w * silu * uacc;
    }
}

// ---------------------------------------------------------------------------
// Kernel 2: out[h] = sum_e dot(down[ex_e][h][:], g_inter[e][:])
// grid: HIDDEN = 2048 blocks, block: 128 threads (4 warps, 1 expert per warp)
// ---------------------------------------------------------------------------
__global__ __launch_bounds__(128)
void moe_down_kernel(const int*   __restrict__ topk_idx,
                     const float* __restrict__ down_all,
                     float*       __restrict__ out)
{
    __shared__ float partial[4];

    const int tid  = threadIdx.x;
    const int lane = tid & 31;
    const int e    = tid >> 5;       // expert slot 0..3
    const int h    = blockIdx.x;     // output element 0..2047

    const long long ex = topk_idx[e];
    const float4* d4 = reinterpret_cast<const float4*>(
        down_all + (ex * HIDDEN + h) * (long long)INTER);
    const float4* i4 = reinterpret_cast<const float4*>(g_inter + e * INTER);

    float acc = 0.f;
    // 352 float4 per row, 32 lanes -> 11 iterations
#pragma unroll
    for (int j = 0; j < 11; j++) {
        const int idx = j * 32 + lane;
        const float4 dv = d4[idx];
        const float4 iv = i4[idx];
        acc += dv.x * iv.x + dv.y * iv.y + dv.z * iv.z + dv.w * iv.w;
    }

#pragma unroll
    for (int off = 16; off > 0; off >>= 1)
        acc += __shfl_xor_sync(0xFFFFFFFFu, acc, off);

    if (lane == 0) partial[e] = acc;
    __syncthreads();

    if (tid == 0)
        out[h] = partial[0] + partial[1] + partial[2] + partial[3];
}

extern "C" void kernel_launch(void* const* d_in, const int* in_sizes, int n_in,
                              void* d_out, int out_size)
{
    const float* x        = (const float*)d_in[0];   // (1, 2048, 1, 1)
    const int*   topk_idx = (const int*)  d_in[1];   // (4,)
    const float* topk_w   = (const float*)d_in[2];   // (4,)
    const float* gate_all = (const float*)d_in[3];   // (60, 1408, 2048)
    const float* up_all   = (const float*)d_in[4];   // (60, 1408, 2048)
    const float* down_all = (const float*)d_in[5];   // (60, 2048, 1408)
    float* out = (float*)d_out;                      // (1, 2048, 1, 1)

    dim3 grid1(INTER / 8, TOP_K);
    moe_gate_up_kernel<<<grid1, 256>>>(x, topk_idx, topk_w, gate_all, up_all);
    moe_down_kernel<<<HIDDEN, 128>>>(topk_idx, down_all, out);
}